// round 16
// baseline (speedup 1.0000x reference)
#include <cuda_runtime.h>
#include <cuda_bf16.h>

#define CCH 256        // channels
#define LV 2           // levels
#define NP 4           // points
#define NOFF 16        // offset outputs (LV*NP*2)
#define NAW 8          // attn outputs (LV*NP)
#define NOUT 24        // total projection outputs
#define NKT 32         // k-tiles (256 / 8)
#define NNT 3          // n-tiles (24 / 8)
#define K1_WARPS 8     // proj warps per block (128 queries/block)
#define QPB2 4         // queries per block (sampling kernel, warp-pair split)

// Scratch: per-query params {16 pre-added pixel coords, 8 normalized attn w}.
__device__ float g_P[1 << 21];   // 8.4 MB

__device__ __forceinline__ unsigned f2tf32(float f) {
    unsigned r;
    asm("cvt.rna.tf32.f32 %0, %1;" : "=r"(r) : "f"(f));
    return r;
}

__device__ __forceinline__ void mma_tf32(float d[4],
                                         unsigned a0, unsigned a1,
                                         unsigned a2, unsigned a3,
                                         unsigned b0, unsigned b1) {
    asm("mma.sync.aligned.m16n8k8.row.col.f32.tf32.tf32.f32 "
        "{%0,%1,%2,%3}, {%4,%5,%6,%7}, {%8,%9}, {%0,%1,%2,%3};"
        : "+f"(d[0]), "+f"(d[1]), "+f"(d[2]), "+f"(d[3])
        : "r"(a0), "r"(a1), "r"(a2), "r"(a3), "r"(b0), "r"(b1));
}

// ---------------------------------------------------------------------------
// Kernel 1: projection + softmax via tf32 MMA.  (unchanged — proven 18.1us)
// ---------------------------------------------------------------------------
__global__ __launch_bounds__(K1_WARPS * 32)
void proj_kernel(const float* __restrict__ query,
                 const float* __restrict__ refpts,
                 const int*   __restrict__ shapes_raw,
                 const float* __restrict__ W_off,  const float* __restrict__ b_off,
                 const float* __restrict__ W_attn, const float* __restrict__ b_attn,
                 int Q)
{
    __shared__ unsigned b0sm[NKT * NNT * 32];         // 12KB
    __shared__ unsigned b1sm[NKT * NNT * 32];         // 12KB
    __shared__ float    csm[K1_WARPS][16][28];        // 14KB epilogue staging

    for (int idx = threadIdx.x; idx < NKT * NNT * 32; idx += K1_WARPS * 32) {
        const int ln   = idx & 31;
        const int pair = idx >> 5;
        const int kt   = pair / 3;
        const int nt   = pair - kt * 3;
        const int tig  = ln & 3;
        const int gid  = ln >> 2;
        const int n    = nt * 8 + gid;
        const int k0   = 32 * (kt >> 2) + 4 * tig + (kt & 3);
        const int k1   = k0 + 16;
        float w0, w1;
        if (n < NOFF) {
            w0 = __ldg(W_off + k0 * NOFF + n);
            w1 = __ldg(W_off + k1 * NOFF + n);
        } else {
            w0 = __ldg(W_attn + k0 * NAW + (n - NOFF));
            w1 = __ldg(W_attn + k1 * NAW + (n - NOFF));
        }
        b0sm[idx] = f2tf32(w0);
        b1sm[idx] = f2tf32(w1);
    }
    __syncthreads();

    const int tid  = threadIdx.x;
    const int lane = tid & 31;
    const int warp = tid >> 5;
    const int gid  = lane >> 2;
    const int tig  = lane & 3;

    const int qbase = blockIdx.x * (K1_WARPS * 16) + warp * 16;
    const int qr0 = min(qbase + gid,     Q - 1);
    const int qr1 = min(qbase + gid + 8, Q - 1);
    const float4* q0p = (const float4*)(query + (size_t)qr0 * CCH) + tig;
    const float4* q1p = (const float4*)(query + (size_t)qr1 * CCH) + tig;

    float d[NNT][4];
#pragma unroll
    for (int nt = 0; nt < NNT; nt++)
#pragma unroll
        for (int i = 0; i < 4; i++) d[nt][i] = 0.f;

#pragma unroll
    for (int kt8 = 0; kt8 < NKT / 8; kt8++) {
        const float4 e0lo = __ldg(q0p + kt8 * 16);
        const float4 e0hi = __ldg(q0p + kt8 * 16 + 4);
        const float4 e1lo = __ldg(q1p + kt8 * 16);
        const float4 e1hi = __ldg(q1p + kt8 * 16 + 4);
        const float4 o0lo = __ldg(q0p + kt8 * 16 + 8);
        const float4 o0hi = __ldg(q0p + kt8 * 16 + 12);
        const float4 o1lo = __ldg(q1p + kt8 * 16 + 8);
        const float4 o1hi = __ldg(q1p + kt8 * 16 + 12);

        const int base_e = (kt8 * 8) * (NNT * 32) + lane;
        const int base_o = base_e + 4 * (NNT * 32);

#define PSTEP(BASE, R0LO, R0HI, R1LO, R1HI, I, C)                              \
        do {                                                                   \
            const unsigned a0 = f2tf32(R0LO.C);                                \
            const unsigned a1 = f2tf32(R1LO.C);                                \
            const unsigned a2 = f2tf32(R0HI.C);                                \
            const unsigned a3 = f2tf32(R1HI.C);                                \
            const int bb = (BASE) + I * (NNT * 32);                            \
            mma_tf32(d[0], a0, a1, a2, a3, b0sm[bb],      b1sm[bb]);           \
            mma_tf32(d[1], a0, a1, a2, a3, b0sm[bb + 32], b1sm[bb + 32]);      \
            mma_tf32(d[2], a0, a1, a2, a3, b0sm[bb + 64], b1sm[bb + 64]);      \
        } while (0)

        PSTEP(base_e, e0lo, e0hi, e1lo, e1hi, 0, x);
        PSTEP(base_e, e0lo, e0hi, e1lo, e1hi, 1, y);
        PSTEP(base_e, e0lo, e0hi, e1lo, e1hi, 2, z);
        PSTEP(base_e, e0lo, e0hi, e1lo, e1hi, 3, w);
        PSTEP(base_o, o0lo, o0hi, o1lo, o1hi, 0, x);
        PSTEP(base_o, o0lo, o0hi, o1lo, o1hi, 1, y);
        PSTEP(base_o, o0lo, o0hi, o1lo, o1hi, 2, z);
        PSTEP(base_o, o0lo, o0hi, o1lo, o1hi, 3, w);
#undef PSTEP
    }

#pragma unroll
    for (int nt = 0; nt < NNT; nt++) {
        const int col = nt * 8 + 2 * tig;
        csm[warp][gid][col]         = d[nt][0];
        csm[warp][gid][col + 1]     = d[nt][1];
        csm[warp][gid + 8][col]     = d[nt][2];
        csm[warp][gid + 8][col + 1] = d[nt][3];
    }
    __syncwarp();

    if (lane < 16) {
        const int q = qbase + lane;
        if (q < Q) {
            float p[NOUT];
#pragma unroll
            for (int j = 0; j < NOUT; j++) p[j] = csm[warp][lane][j];
#pragma unroll
            for (int j = 0; j < NOFF; j++) p[j] += __ldg(b_off + j);
#pragma unroll
            for (int j = 0; j < NAW; j++)  p[NOFF + j] += __ldg(b_attn + j);

            {
                const int st = (__ldg(shapes_raw + 1) == 0) ? 2 : 1;
                const float* ref = refpts + (size_t)q * (LV * 2);
#pragma unroll
                for (int l = 0; l < LV; l++) {
                    const float Hf = (float)__ldg(shapes_raw + (2 * l) * st);
                    const float Wf = (float)__ldg(shapes_raw + (2 * l + 1) * st);
                    const float bx = __ldg(ref + 2 * l)     * Wf - 0.5f;
                    const float by = __ldg(ref + 2 * l + 1) * Hf - 0.5f;
#pragma unroll
                    for (int pt = 0; pt < NP; pt++) {
                        p[l * 8 + pt * 2]     += bx;
                        p[l * 8 + pt * 2 + 1] += by;
                    }
                }
            }

            float m = p[NOFF];
#pragma unroll
            for (int j = 1; j < NAW; j++) m = fmaxf(m, p[NOFF + j]);
            float s = 0.f;
#pragma unroll
            for (int j = 0; j < NAW; j++) {
                const float e = __expf(p[NOFF + j] - m);
                p[NOFF + j] = e;
                s += e;
            }
            const float inv = 1.f / s;
#pragma unroll
            for (int j = 0; j < NAW; j++) p[NOFF + j] *= inv;

            float4* o4 = (float4*)(g_P + (size_t)q * NOUT);
#pragma unroll
            for (int i = 0; i < 6; i++)
                o4[i] = make_float4(p[4 * i], p[4 * i + 1],
                                    p[4 * i + 2], p[4 * i + 3]);
        }
    }
}

// ---------------------------------------------------------------------------
// Kernel 2: bilinear sampling, warp-PAIR per query (one level per warp).
// Halves each warp's serial gather chain; level-1 partial combined via smem.
// ---------------------------------------------------------------------------
__global__ __launch_bounds__(256, 6)
void sample_kernel(const float* __restrict__ value,
                   const int*   __restrict__ shapes_raw,
                   float* __restrict__ out, int Q)
{
    __shared__ float ssum[QPB2][CCH];   // 4KB: level-1 partial sums

    const int tid  = threadIdx.x;
    const int lane = tid & 31;
    const int warp = tid >> 5;
    const int qloc = warp >> 1;     // query within block (0..3)
    const int lvl  = warp & 1;      // level this warp handles
    const int q = blockIdx.x * QPB2 + qloc;
    const bool active = (q < Q);

    int HH[LV], WW[LV];
    {
        const int st = (__ldg(shapes_raw + 1) == 0) ? 2 : 1;
#pragma unroll
        for (int l = 0; l < LV; l++) {
            HH[l] = __ldg(shapes_raw + (2 * l) * st);
            WW[l] = __ldg(shapes_raw + (2 * l + 1) * st);
        }
    }
    const float4* vb4 = (const float4*)value;

    float4 acc0 = make_float4(0.f, 0.f, 0.f, 0.f);
    float4 acc1 = make_float4(0.f, 0.f, 0.f, 0.f);

    if (active) {
        const float4* pf = (const float4*)(g_P + (size_t)q * NOUT);
        const int Hs = HH[lvl], Ws = WW[lvl];
        const unsigned loff4 = lvl ? (unsigned)(HH[0] * WW[0]) * 64u : 0u;

        const float4 oA = __ldg(pf + 2 * lvl);       // ix/iy pts 0,1
        const float4 oB = __ldg(pf + 2 * lvl + 1);   // ix/iy pts 2,3
        const float4 wv = __ldg(pf + 4 + lvl);       // 4 normalized attn weights

        const float ixs[NP] = {oA.x, oA.z, oB.x, oB.z};
        const float iys[NP] = {oA.y, oA.w, oB.y, oB.w};
        const float aws[NP] = {wv.x, wv.y, wv.z, wv.w};

        int x0[NP], y0[NP];
#pragma unroll
        for (int pt = 0; pt < NP; pt++) {
            x0[pt] = (int)floorf(ixs[pt]);
            y0[pt] = (int)floorf(iys[pt]);
        }

        const int xmin = min(min(x0[0], x0[1]), min(x0[2], x0[3]));
        const int ymin = min(min(y0[0], y0[1]), min(y0[2], y0[3]));
        const int xmax = max(max(x0[0], x0[1]), max(x0[2], x0[3]));
        const int ymax = max(max(y0[0], y0[1]), max(y0[2], y0[3]));

        float    myw   = 0.f;
        unsigned myoff = 0;

#define GATHER_NOW(OFF4, W)                                                    \
        do {                                                                   \
            const float4 v0 = __ldg(vb4 + (OFF4) + lane);                      \
            const float4 v1 = __ldg(vb4 + (OFF4) + 32 + lane);                 \
            acc0.x = fmaf((W), v0.x, acc0.x);                                  \
            acc0.y = fmaf((W), v0.y, acc0.y);                                  \
            acc0.z = fmaf((W), v0.z, acc0.z);                                  \
            acc0.w = fmaf((W), v0.w, acc0.w);                                  \
            acc1.x = fmaf((W), v1.x, acc1.x);                                  \
            acc1.y = fmaf((W), v1.y, acc1.y);                                  \
            acc1.z = fmaf((W), v1.z, acc1.z);                                  \
            acc1.w = fmaf((W), v1.w, acc1.w);                                  \
        } while (0)

        if (xmax - xmin <= 2 && ymax - ymin <= 2) {
            // Fast path: 16 cells in a 4x4 window; lane<16 owns cell lane.
            if (lane < 16) {
                const int xx = xmin + (lane & 3);
                const int yy = ymin + (lane >> 2);
                const float Xc = (float)xx;
                const float Yc = (float)yy;
                float w = 0.f;
#pragma unroll
                for (int pt = 0; pt < NP; pt++) {
                    const float wx = fmaxf(0.f, 1.f - fabsf(ixs[pt] - Xc));
                    const float wy = fmaxf(0.f, 1.f - fabsf(iys[pt] - Yc));
                    w = fmaf(aws[pt] * wx, wy, w);
                }
                const bool ok = (unsigned)xx < (unsigned)Ws &&
                                (unsigned)yy < (unsigned)Hs;
                myw = ok ? w : 0.f;
                const int xc = min(max(xx, 0), Ws - 1);
                const int yc = min(max(yy, 0), Hs - 1);
                myoff = loff4 + (((unsigned)(yc * Ws + xc)) << 6);
            }
        } else {
            // Rare fallback: immediate per-corner gathers.
#pragma unroll
            for (int pt = 0; pt < NP; pt++) {
                const float x0f = floorf(ixs[pt]);
                const float y0f = floorf(iys[pt]);
                const float fx = ixs[pt] - x0f;
                const float fy = iys[pt] - y0f;
                const float a  = aws[pt];
                const float cw[4] = {(1.f - fx) * (1.f - fy) * a,
                                     fx * (1.f - fy) * a,
                                     (1.f - fx) * fy * a,
                                     fx * fy * a};
                const int xs[2] = {x0[pt], x0[pt] + 1};
                const int ys[2] = {y0[pt], y0[pt] + 1};
#pragma unroll
                for (int cy = 0; cy < 2; cy++) {
#pragma unroll
                    for (int cx = 0; cx < 2; cx++) {
                        const int xx = xs[cx];
                        const int yy = ys[cy];
                        const float w = cw[cy * 2 + cx];
                        if ((unsigned)xx < (unsigned)Ws && (unsigned)yy < (unsigned)Hs) {
                            const unsigned off4 =
                                loff4 + (((unsigned)(yy * Ws + xx)) << 6);
                            GATHER_NOW(off4, w);
                        }
                    }
                }
            }
        }

        // Gather loop: 2 cells per iteration, loads batched.
        unsigned nz = __ballot_sync(0xffffffffu, myw != 0.f);
        while (nz) {
            int c0 = __ffs(nz) - 1; nz &= nz - 1;
            int c1 = __ffs(nz) - 1; nz &= nz - 1;

            float    w0 = __shfl_sync(0xffffffffu, myw,   c0 & 31);
            unsigned f0 = __shfl_sync(0xffffffffu, myoff, c0 & 31);
            float    w1 = __shfl_sync(0xffffffffu, myw,   c1 & 31);
            unsigned f1 = __shfl_sync(0xffffffffu, myoff, c1 & 31);
            if (c1 < 0) w1 = 0.f;

            float4 a1 = make_float4(0.f,0.f,0.f,0.f), b1 = a1;
            const float4 a0 = __ldg(vb4 + f0 + lane);
            const float4 b0 = __ldg(vb4 + f0 + 32 + lane);
            if (c1 >= 0) {
                a1 = __ldg(vb4 + f1 + lane);
                b1 = __ldg(vb4 + f1 + 32 + lane);
            }

            acc0.x = fmaf(w0, a0.x, acc0.x); acc0.y = fmaf(w0, a0.y, acc0.y);
            acc0.z = fmaf(w0, a0.z, acc0.z); acc0.w = fmaf(w0, a0.w, acc0.w);
            acc1.x = fmaf(w0, b0.x, acc1.x); acc1.y = fmaf(w0, b0.y, acc1.y);
            acc1.z = fmaf(w0, b0.z, acc1.z); acc1.w = fmaf(w0, b0.w, acc1.w);

            acc0.x = fmaf(w1, a1.x, acc0.x); acc0.y = fmaf(w1, a1.y, acc0.y);
            acc0.z = fmaf(w1, a1.z, acc0.z); acc0.w = fmaf(w1, a1.w, acc0.w);
            acc1.x = fmaf(w1, b1.x, acc1.x); acc1.y = fmaf(w1, b1.y, acc1.y);
            acc1.z = fmaf(w1, b1.z, acc1.z); acc1.w = fmaf(w1, b1.w, acc1.w);
        }
#undef GATHER_NOW
    }

    // Combine: level-1 warp parks its partial in smem; level-0 warp adds+stores.
    if (lvl == 1 && active) {
        float4* sp = (float4*)&ssum[qloc][0];
        sp[lane]      = acc0;
        sp[32 + lane] = acc1;
    }
    __syncthreads();
    if (lvl == 0 && active) {
        const float4* sp = (const float4*)&ssum[qloc][0];
        const float4 p0 = sp[lane];
        const float4 p1 = sp[32 + lane];
        acc0.x += p0.x; acc0.y += p0.y; acc0.z += p0.z; acc0.w += p0.w;
        acc1.x += p1.x; acc1.y += p1.y; acc1.z += p1.z; acc1.w += p1.w;

        float4* op = (float4*)(out + (size_t)q * CCH);
        op[lane]      = acc0;   // channels [4*lane, 4*lane+4)
        op[32 + lane] = acc1;   // channels [128+4*lane, ...)
    }
}

extern "C" void kernel_launch(void* const* d_in, const int* in_sizes, int n_in,
                              void* d_out, int out_size)
{
    const float* query   = (const float*)d_in[0];
    // d_in[1] = key (unused)
    const float* value   = (const float*)d_in[2];
    const float* refpts  = (const float*)d_in[3];
    const int*   shapes  = (const int*)d_in[4];
    const float* W_off   = (const float*)d_in[5];
    const float* b_off   = (const float*)d_in[6];
    const float* W_attn  = (const float*)d_in[7];
    const float* b_attn  = (const float*)d_in[8];
    float*       out     = (float*)d_out;

    const int Q = in_sizes[0] / CCH;

    const int qpb = K1_WARPS * 16;
    proj_kernel<<<(Q + qpb - 1) / qpb, K1_WARPS * 32>>>(
        query, refpts, shapes, W_off, b_off, W_attn, b_attn, Q);
    sample_kernel<<<(Q + QPB2 - 1) / QPB2, 256>>>(
        value, shapes, out, Q);
}